// round 4
// baseline (speedup 1.0000x reference)
#include <cuda_runtime.h>
#include <cuda_fp16.h>
#include <cstdint>

#define NTOT   100000
#define KNEI   16
#define XNIN   128
#define XEIN   64
#define XNOUT  128
#define KTOT   320      // 128 (x) + 128 (xnj) + 64 (xej)
#define AS     328      // smem row stride in halves: 164 words, 164%32=4 -> conflict-free
#define ROWS_PER_CTA 128

// Scratch (device globals — allocation-free per harness rules)
__device__ __half g_xh[(size_t)NTOT * XNIN];      // fp16 copy of x (25.6 MB)
__device__ __half g_A2[(size_t)NTOT * 192];       // fp16 [gather-mean(128) | e-mean(64)]
__device__ __half g_wh[XNOUT * KTOT];             // packed fp16 [Wc|Wn|We], row-major (n,k)

// ---------------------------------------------------------------------------
// Kernel 1: quantize x -> fp16, pack weights -> fp16
// ---------------------------------------------------------------------------
__global__ void prep_kernel(const float* __restrict__ x,
                            const float* __restrict__ Wc,
                            const float* __restrict__ Wn,
                            const float* __restrict__ We) {
    int tid = blockIdx.x * blockDim.x + threadIdx.x;
    int stride = gridDim.x * blockDim.x;

    const float4* x4 = (const float4*)x;
    __half2* xh2 = (__half2*)g_xh;
    const int total4 = NTOT * XNIN / 4;
    for (int i = tid; i < total4; i += stride) {
        float4 v = __ldcs(&x4[i]);
        xh2[2 * i]     = __floats2half2_rn(v.x, v.y);
        xh2[2 * i + 1] = __floats2half2_rn(v.z, v.w);
    }

    for (int i = tid; i < XNOUT * KTOT; i += stride) {
        int n = i / KTOT, k = i % KTOT;
        float w = (k < 128) ? Wc[n * 128 + k]
                : (k < 256) ? Wn[n * 128 + (k - 128)]
                            : We[n * 64 + (k - 256)];
        g_wh[i] = __float2half(w);
    }
}

// ---------------------------------------------------------------------------
// Kernel 2: build A2 = [ mean_k x_h[nh[r,k]] (128) | mean_k e[r,k,:] (64) ]
// One warp per row, grid-stride. Zero smem -> max occupancy, huge MLP.
// Streaming loads (e, ij) use __ldcs so they do not evict the L2-resident
// gather table g_xh.
// ---------------------------------------------------------------------------
__global__ void __launch_bounds__(256)
build_kernel(const float* __restrict__ e,
             const int* __restrict__ ij) {
    const int lane   = threadIdx.x & 31;
    const int warpId = (blockIdx.x * blockDim.x + threadIdx.x) >> 5;
    const int nWarps = (gridDim.x * blockDim.x) >> 5;

    for (int r = warpId; r < NTOT; r += nWarps) {
        // indices: ij[r, k, 0] for k = lane (< 16)
        int idx = 0;
        if (lane < KNEI) idx = __ldcs(&ij[((size_t)r * KNEI + lane) * 2]);

        // ---- gather-mean: lane owns cols 4*lane .. 4*lane+3 (L2 hits) ----
        uint2 vals[KNEI];
        #pragma unroll
        for (int k = 0; k < KNEI; k++) {
            int nb = __shfl_sync(0xffffffffu, idx, k);
            nb = (nb < 0) ? 0 : ((nb >= NTOT) ? (NTOT - 1) : nb);
            vals[k] = *(const uint2*)&g_xh[(size_t)nb * XNIN + lane * 4];
        }

        // ---- e-mean: lane owns cols 2*lane .. 2*lane+1 (streaming) ----
        float2 evals[KNEI];
        const float2* ebase = (const float2*)(e + (size_t)r * (KNEI * XEIN)) + lane;
        #pragma unroll
        for (int k = 0; k < KNEI; k++)
            evals[k] = __ldcs(ebase + k * (XEIN / 2));

        float f0 = 0.f, f1 = 0.f, f2 = 0.f, f3 = 0.f;
        #pragma unroll
        for (int k = 0; k < KNEI; k++) {
            float2 a = __half22float2(*(__half2*)&vals[k].x);
            float2 b = __half22float2(*(__half2*)&vals[k].y);
            f0 += a.x; f1 += a.y; f2 += b.x; f3 += b.y;
        }
        float s0 = 0.f, s1 = 0.f;
        #pragma unroll
        for (int k = 0; k < KNEI; k++) { s0 += evals[k].x; s1 += evals[k].y; }

        __half* arow = &g_A2[(size_t)r * 192];
        uint2 gpack;
        *(__half2*)&gpack.x = __floats2half2_rn(f0 * 0.0625f, f1 * 0.0625f);
        *(__half2*)&gpack.y = __floats2half2_rn(f2 * 0.0625f, f3 * 0.0625f);
        *(uint2*)&arow[lane * 4] = gpack;
        *(__half2*)&arow[128 + lane * 2] = __floats2half2_rn(s0 * 0.0625f, s1 * 0.0625f);
    }
}

// ---------------------------------------------------------------------------
// Kernel 3: GEMM  out = relu( [xh | A2] @ [Wc|Wn|We]^T )
// A-tile in smem (84 KB) only; W read from global (L2/L1-resident, 80 KB).
// 2 CTAs/SM -> cross-CTA overlap of load phase and MMA phase.
// ---------------------------------------------------------------------------
extern __shared__ __half smem[];

__global__ void __launch_bounds__(512, 2)
gemm_kernel(float* __restrict__ out) {
    __half* Asm = smem;                       // [128][AS]

    const int tid  = threadIdx.x;
    const int lane = tid & 31;
    const int warp = tid >> 5;
    const int r0   = blockIdx.x * ROWS_PER_CTA;

    // ---- A[:, 0:128] = xh rows ----
    for (int i = tid; i < 2048; i += 512) {     // 128 rows * 16 int4
        int m = i >> 4, c = i & 15;
        int r = r0 + m;
        int4 v = make_int4(0, 0, 0, 0);
        if (r < NTOT) v = *(const int4*)&g_xh[(size_t)r * XNIN + c * 8];
        *(int4*)&Asm[m * AS + c * 8] = v;
    }

    // ---- A[:, 128:320] = A2 rows ----
    for (int i = tid; i < 3072; i += 512) {     // 128 rows * 24 int4
        int m = i / 24, c = i % 24;
        int r = r0 + m;
        int4 v = make_int4(0, 0, 0, 0);
        if (r < NTOT) v = *(const int4*)&g_A2[(size_t)r * 192 + c * 8];
        *(int4*)&Asm[m * AS + 128 + c * 8] = v;
    }

    __syncthreads();

    // ---- MMA: warp (mt, nh) computes rows [mt*16, +16) x cols [nh*64, +64) ----
    const int g  = lane >> 2;
    const int tg = lane & 3;
    const int mt = warp >> 1;
    const int nh = warp & 1;
    const int wm = mt * 16;

    float acc[8][4];
    #pragma unroll
    for (int t = 0; t < 8; t++)
        acc[t][0] = acc[t][1] = acc[t][2] = acc[t][3] = 0.f;

    #pragma unroll 2
    for (int k0 = 0; k0 < KTOT; k0 += 16) {
        uint32_t a0 = *(const uint32_t*)&Asm[(wm + g)     * AS + k0 +     tg * 2];
        uint32_t a1 = *(const uint32_t*)&Asm[(wm + g + 8) * AS + k0 +     tg * 2];
        uint32_t a2 = *(const uint32_t*)&Asm[(wm + g)     * AS + k0 + 8 + tg * 2];
        uint32_t a3 = *(const uint32_t*)&Asm[(wm + g + 8) * AS + k0 + 8 + tg * 2];
        #pragma unroll
        for (int t = 0; t < 8; t++) {
            int nrow = nh * 64 + t * 8 + g;
            uint32_t b0 = __ldg((const uint32_t*)&g_wh[nrow * KTOT + k0 +     tg * 2]);
            uint32_t b1 = __ldg((const uint32_t*)&g_wh[nrow * KTOT + k0 + 8 + tg * 2]);
            asm volatile(
                "mma.sync.aligned.m16n8k16.row.col.f32.f16.f16.f32 "
                "{%0,%1,%2,%3},{%4,%5,%6,%7},{%8,%9},{%0,%1,%2,%3};\n"
                : "+f"(acc[t][0]), "+f"(acc[t][1]), "+f"(acc[t][2]), "+f"(acc[t][3])
                : "r"(a0), "r"(a1), "r"(a2), "r"(a3), "r"(b0), "r"(b1));
        }
    }

    // ---- Store with relu (streaming: don't evict xh/W from L2) ----
    #pragma unroll
    for (int t = 0; t < 8; t++) {
        int col  = nh * 64 + t * 8 + tg * 2;
        int row0 = r0 + wm + g;
        int row1 = row0 + 8;
        if (row0 < NTOT) {
            float2 v;
            v.x = fmaxf(acc[t][0], 0.f);
            v.y = fmaxf(acc[t][1], 0.f);
            __stcs((float2*)&out[(size_t)row0 * XNOUT + col], v);
        }
        if (row1 < NTOT) {
            float2 v;
            v.x = fmaxf(acc[t][2], 0.f);
            v.y = fmaxf(acc[t][3], 0.f);
            __stcs((float2*)&out[(size_t)row1 * XNOUT + col], v);
        }
    }
}

// ---------------------------------------------------------------------------
extern "C" void kernel_launch(void* const* d_in, const int* in_sizes, int n_in,
                              void* d_out, int out_size) {
    const float* x  = (const float*)d_in[0];
    const float* e  = (const float*)d_in[1];
    const int*   ij = (const int*)d_in[2];     // int32 (JAX x64 disabled)
    const float* Wc = (const float*)d_in[3];
    const float* Wn = (const float*)d_in[4];
    const float* We = (const float*)d_in[5];
    float* out = (float*)d_out;
    (void)in_sizes; (void)n_in; (void)out_size;

    prep_kernel<<<2048, 256>>>(x, Wc, Wn, We);

    build_kernel<<<2048, 256>>>(e, ij);

    const int smem_bytes = ROWS_PER_CTA * AS * (int)sizeof(__half);  // 83968
    cudaFuncSetAttribute(gemm_kernel,
                         cudaFuncAttributeMaxDynamicSharedMemorySize, smem_bytes);
    int nblk = (NTOT + ROWS_PER_CTA - 1) / ROWS_PER_CTA;   // 782
    gemm_kernel<<<nblk, 512, smem_bytes>>>(out);
}

// round 5
// speedup vs baseline: 1.6524x; 1.6524x over previous
#include <cuda_runtime.h>
#include <cuda_fp16.h>
#include <cstdint>

#define NTOT   100000
#define KNEI   16
#define XNIN   128
#define XEIN   64
#define XNOUT  128
#define KTOT   320      // 128 (x) + 128 (xnj) + 64 (xej)
#define AS     328      // smem row stride in halves: 164 words, 164%32=4 -> conflict-free
#define ROWS_PER_CTA 128

// Scratch (device globals — allocation-free per harness rules)
__device__ __half g_xh[(size_t)NTOT * XNIN];      // fp16 copy of x (25.6 MB)
__device__ __half g_A2[(size_t)NTOT * 192];       // fp16 [gather-mean(128) | e-mean(64)]
__device__ __half g_wh[XNOUT * KTOT];             // packed fp16 [Wc|Wn|We], row-major (n,k)

// ---------------------------------------------------------------------------
// Kernel 1: quantize x -> fp16, pack weights -> fp16
// ---------------------------------------------------------------------------
__global__ void prep_kernel(const float* __restrict__ x,
                            const float* __restrict__ Wc,
                            const float* __restrict__ Wn,
                            const float* __restrict__ We) {
    int tid = blockIdx.x * blockDim.x + threadIdx.x;
    int stride = gridDim.x * blockDim.x;

    const float4* x4 = (const float4*)x;
    __half2* xh2 = (__half2*)g_xh;
    const int total4 = NTOT * XNIN / 4;
    for (int i = tid; i < total4; i += stride) {
        float4 v = __ldcs(&x4[i]);
        xh2[2 * i]     = __floats2half2_rn(v.x, v.y);
        xh2[2 * i + 1] = __floats2half2_rn(v.z, v.w);
    }

    for (int i = tid; i < XNOUT * KTOT; i += stride) {
        int n = i / KTOT, k = i % KTOT;
        float w = (k < 128) ? Wc[n * 128 + k]
                : (k < 256) ? Wn[n * 128 + (k - 128)]
                            : We[n * 64 + (k - 256)];
        g_wh[i] = __float2half(w);
    }
}

// ---------------------------------------------------------------------------
// Kernel 2: build A2 = [ mean_k x_h[nh[r,k]] (128) | mean_k e[r,k,:] (64) ]
// One warp per row, grid-stride, software-pipelined ij prefetch.
// Streaming loads (e, ij) use __ldcs so they don't evict g_xh from L2.
// ---------------------------------------------------------------------------
__global__ void __launch_bounds__(256)
build_kernel(const float* __restrict__ e,
             const int* __restrict__ ij) {
    const int lane   = threadIdx.x & 31;
    const int warpId = (blockIdx.x * blockDim.x + threadIdx.x) >> 5;
    const int nWarps = (gridDim.x * blockDim.x) >> 5;

    // Prefetch indices for the first row (breaks ij-latency out of the chain)
    int r = warpId;
    int idx = 0;
    if (r < NTOT && lane < KNEI)
        idx = __ldcs(&ij[((size_t)r * KNEI + lane) * 2]);

    for (; r < NTOT; r += nWarps) {
        // ---- prefetch ij for next row (independent of this row's work) ----
        const int rn = r + nWarps;
        int idx_next = 0;
        if (rn < NTOT && lane < KNEI)
            idx_next = __ldcs(&ij[((size_t)rn * KNEI + lane) * 2]);

        // ---- e-mean loads (independent, issue early): lane owns 2 cols ----
        float2 evals[KNEI];
        const float2* ebase = (const float2*)(e + (size_t)r * (KNEI * XEIN)) + lane;
        #pragma unroll
        for (int k = 0; k < KNEI; k++)
            evals[k] = __ldcs(ebase + k * (XEIN / 2));

        // ---- gather-mean: lane owns cols 4*lane .. 4*lane+3 (L2 hits) ----
        uint2 vals[KNEI];
        #pragma unroll
        for (int k = 0; k < KNEI; k++) {
            int nb = __shfl_sync(0xffffffffu, idx, k);
            nb = (nb < 0) ? 0 : ((nb >= NTOT) ? (NTOT - 1) : nb);
            vals[k] = *(const uint2*)&g_xh[(size_t)nb * XNIN + lane * 4];
        }

        float f0 = 0.f, f1 = 0.f, f2 = 0.f, f3 = 0.f;
        #pragma unroll
        for (int k = 0; k < KNEI; k++) {
            float2 a = __half22float2(*(__half2*)&vals[k].x);
            float2 b = __half22float2(*(__half2*)&vals[k].y);
            f0 += a.x; f1 += a.y; f2 += b.x; f3 += b.y;
        }
        float s0 = 0.f, s1 = 0.f;
        #pragma unroll
        for (int k = 0; k < KNEI; k++) { s0 += evals[k].x; s1 += evals[k].y; }

        __half* arow = &g_A2[(size_t)r * 192];
        uint2 gpack;
        *(__half2*)&gpack.x = __floats2half2_rn(f0 * 0.0625f, f1 * 0.0625f);
        *(__half2*)&gpack.y = __floats2half2_rn(f2 * 0.0625f, f3 * 0.0625f);
        *(uint2*)&arow[lane * 4] = gpack;
        *(__half2*)&arow[128 + lane * 2] = __floats2half2_rn(s0 * 0.0625f, s1 * 0.0625f);

        idx = idx_next;
    }
}

// ---------------------------------------------------------------------------
// Kernel 3: GEMM  out = relu( [xh | A2] @ [Wc|Wn|We]^T )  (R3 form: W in smem)
// 512 threads: 16 warps = 8 m-tiles x 2 n-halves. Coalesced loads only.
// ---------------------------------------------------------------------------
extern __shared__ __half smem[];

__global__ void __launch_bounds__(512, 1)
gemm_kernel(float* __restrict__ out) {
    __half* Asm = smem;                       // [128][AS]
    __half* Wsm = smem + ROWS_PER_CTA * AS;   // [128][AS]

    const int tid  = threadIdx.x;
    const int lane = tid & 31;
    const int warp = tid >> 5;
    const int r0   = blockIdx.x * ROWS_PER_CTA;

    // ---- W: packed weights -> smem (row-major n, stride AS) ----
    {
        const int4* wsrc = (const int4*)g_wh;   // 5120 int4
        for (int i = tid; i < 5120; i += 512) {
            int row = i / 40, c = i % 40;
            *(int4*)&Wsm[row * AS + c * 8] = wsrc[i];
        }
    }

    // ---- A[:, 0:128] = xh rows ----
    for (int i = tid; i < 2048; i += 512) {     // 128 rows * 16 int4
        int m = i >> 4, c = i & 15;
        int r = r0 + m;
        int4 v = make_int4(0, 0, 0, 0);
        if (r < NTOT) v = *(const int4*)&g_xh[(size_t)r * XNIN + c * 8];
        *(int4*)&Asm[m * AS + c * 8] = v;
    }

    // ---- A[:, 128:320] = A2 rows ----
    for (int i = tid; i < 3072; i += 512) {     // 128 rows * 24 int4
        int m = i / 24, c = i % 24;
        int r = r0 + m;
        int4 v = make_int4(0, 0, 0, 0);
        if (r < NTOT) v = *(const int4*)&g_A2[(size_t)r * 192 + c * 8];
        *(int4*)&Asm[m * AS + 128 + c * 8] = v;
    }

    __syncthreads();

    // ---- MMA: warp (mt, nh) computes rows [mt*16, +16) x cols [nh*64, +64) ----
    const int g  = lane >> 2;
    const int tg = lane & 3;
    const int mt = warp >> 1;
    const int nh = warp & 1;
    const int wm = mt * 16;

    float acc[8][4];
    #pragma unroll
    for (int t = 0; t < 8; t++)
        acc[t][0] = acc[t][1] = acc[t][2] = acc[t][3] = 0.f;

    #pragma unroll 4
    for (int k0 = 0; k0 < KTOT; k0 += 16) {
        uint32_t a0 = *(const uint32_t*)&Asm[(wm + g)     * AS + k0 +     tg * 2];
        uint32_t a1 = *(const uint32_t*)&Asm[(wm + g + 8) * AS + k0 +     tg * 2];
        uint32_t a2 = *(const uint32_t*)&Asm[(wm + g)     * AS + k0 + 8 + tg * 2];
        uint32_t a3 = *(const uint32_t*)&Asm[(wm + g + 8) * AS + k0 + 8 + tg * 2];
        #pragma unroll
        for (int t = 0; t < 8; t++) {
            int nrow = nh * 64 + t * 8 + g;
            uint32_t b0 = *(const uint32_t*)&Wsm[nrow * AS + k0 +     tg * 2];
            uint32_t b1 = *(const uint32_t*)&Wsm[nrow * AS + k0 + 8 + tg * 2];
            asm volatile(
                "mma.sync.aligned.m16n8k16.row.col.f32.f16.f16.f32 "
                "{%0,%1,%2,%3},{%4,%5,%6,%7},{%8,%9},{%0,%1,%2,%3};\n"
                : "+f"(acc[t][0]), "+f"(acc[t][1]), "+f"(acc[t][2]), "+f"(acc[t][3])
                : "r"(a0), "r"(a1), "r"(a2), "r"(a3), "r"(b0), "r"(b1));
        }
    }

    // ---- Store with relu ----
    #pragma unroll
    for (int t = 0; t < 8; t++) {
        int col  = nh * 64 + t * 8 + tg * 2;
        int row0 = r0 + wm + g;
        int row1 = row0 + 8;
        if (row0 < NTOT) {
            float2 v;
            v.x = fmaxf(acc[t][0], 0.f);
            v.y = fmaxf(acc[t][1], 0.f);
            *(float2*)&out[(size_t)row0 * XNOUT + col] = v;
        }
        if (row1 < NTOT) {
            float2 v;
            v.x = fmaxf(acc[t][2], 0.f);
            v.y = fmaxf(acc[t][3], 0.f);
            *(float2*)&out[(size_t)row1 * XNOUT + col] = v;
        }
    }
}

// ---------------------------------------------------------------------------
// Probe: no-op launch to shift ncu's -s 5 -c 1 capture window onto build_kernel
// ---------------------------------------------------------------------------
__global__ void probe_kernel() {}

// ---------------------------------------------------------------------------
extern "C" void kernel_launch(void* const* d_in, const int* in_sizes, int n_in,
                              void* d_out, int out_size) {
    const float* x  = (const float*)d_in[0];
    const float* e  = (const float*)d_in[1];
    const int*   ij = (const int*)d_in[2];     // int32 (JAX x64 disabled)
    const float* Wc = (const float*)d_in[3];
    const float* Wn = (const float*)d_in[4];
    const float* We = (const float*)d_in[5];
    float* out = (float*)d_out;
    (void)in_sizes; (void)n_in; (void)out_size;

    prep_kernel<<<2048, 256>>>(x, Wc, Wn, We);

    build_kernel<<<2048, 256>>>(e, ij);

    const int smem_bytes = 2 * ROWS_PER_CTA * AS * (int)sizeof(__half);  // 167936
    cudaFuncSetAttribute(gemm_kernel,
                         cudaFuncAttributeMaxDynamicSharedMemorySize, smem_bytes);
    int nblk = (NTOT + ROWS_PER_CTA - 1) / ROWS_PER_CTA;   // 782
    gemm_kernel<<<nblk, 512, smem_bytes>>>(out);

    probe_kernel<<<1, 1>>>();   // shifts ncu capture window; no-op
}

// round 7
// speedup vs baseline: 1.9358x; 1.1715x over previous
#include <cuda_runtime.h>
#include <cuda_fp16.h>
#include <cstdint>

#define NTOT   100000
#define KNEI   16
#define XNIN   128
#define XEIN   64
#define XNOUT  128
#define KTOT   320      // 128 (x) + 128 (xnj) + 64 (xej)
#define AS     328      // smem row stride in halves: bank = 4g+tg, conflict-free
#define CHUNK_ROWS 64
#define NCH    ((NTOT + CHUNK_ROWS - 1) / CHUNK_ROWS)   // 1563
#define GRID_G 152      // GB300: 152 SMs, 1 persistent CTA each

// Scratch (device globals — allocation-free per harness rules)
__device__ __half g_xh[(size_t)NTOT * XNIN];      // fp16 copy of x (25.6 MB)
__device__ __half g_A2[(size_t)NTOT * 192];       // fp16 [gather-mean(128) | e-mean(64)]
__device__ __half g_wh[XNOUT * KTOT];             // packed fp16 [Wc|Wn|We], row-major (n,k)

// ---------------------------------------------------------------------------
// Kernel 1: quantize x -> fp16, pack weights -> fp16
// ---------------------------------------------------------------------------
__global__ void prep_kernel(const float* __restrict__ x,
                            const float* __restrict__ Wc,
                            const float* __restrict__ Wn,
                            const float* __restrict__ We) {
    int tid = blockIdx.x * blockDim.x + threadIdx.x;
    int stride = gridDim.x * blockDim.x;

    const float4* x4 = (const float4*)x;
    __half2* xh2 = (__half2*)g_xh;
    const int total4 = NTOT * XNIN / 4;
    for (int i = tid; i < total4; i += stride) {
        float4 v = __ldcs(&x4[i]);
        xh2[2 * i]     = __floats2half2_rn(v.x, v.y);
        xh2[2 * i + 1] = __floats2half2_rn(v.z, v.w);
    }

    for (int i = tid; i < XNOUT * KTOT; i += stride) {
        int n = i / KTOT, k = i % KTOT;
        float w = (k < 128) ? Wc[n * 128 + k]
                : (k < 256) ? Wn[n * 128 + (k - 128)]
                            : We[n * 64 + (k - 256)];
        g_wh[i] = __float2half(w);
    }
}

// ---------------------------------------------------------------------------
// Kernel 2: build A2 = [ mean_k x_h[nh[r,k]] (128) | mean_k e[r,k,:] (64) ]
// One warp per row, grid-stride, software-pipelined ij prefetch. (R5 form)
// ---------------------------------------------------------------------------
__global__ void __launch_bounds__(256)
build_kernel(const float* __restrict__ e,
             const int* __restrict__ ij) {
    const int lane   = threadIdx.x & 31;
    const int warpId = (blockIdx.x * blockDim.x + threadIdx.x) >> 5;
    const int nWarps = (gridDim.x * blockDim.x) >> 5;

    int r = warpId;
    int idx = 0;
    if (r < NTOT && lane < KNEI)
        idx = __ldcs(&ij[((size_t)r * KNEI + lane) * 2]);

    for (; r < NTOT; r += nWarps) {
        const int rn = r + nWarps;
        int idx_next = 0;
        if (rn < NTOT && lane < KNEI)
            idx_next = __ldcs(&ij[((size_t)rn * KNEI + lane) * 2]);

        float2 evals[KNEI];
        const float2* ebase = (const float2*)(e + (size_t)r * (KNEI * XEIN)) + lane;
        #pragma unroll
        for (int k = 0; k < KNEI; k++)
            evals[k] = __ldcs(ebase + k * (XEIN / 2));

        uint2 vals[KNEI];
        #pragma unroll
        for (int k = 0; k < KNEI; k++) {
            int nb = __shfl_sync(0xffffffffu, idx, k);
            nb = (nb < 0) ? 0 : ((nb >= NTOT) ? (NTOT - 1) : nb);
            vals[k] = *(const uint2*)&g_xh[(size_t)nb * XNIN + lane * 4];
        }

        float f0 = 0.f, f1 = 0.f, f2 = 0.f, f3 = 0.f;
        #pragma unroll
        for (int k = 0; k < KNEI; k++) {
            float2 a = __half22float2(*(__half2*)&vals[k].x);
            float2 b = __half22float2(*(__half2*)&vals[k].y);
            f0 += a.x; f1 += a.y; f2 += b.x; f3 += b.y;
        }
        float s0 = 0.f, s1 = 0.f;
        #pragma unroll
        for (int k = 0; k < KNEI; k++) { s0 += evals[k].x; s1 += evals[k].y; }

        __half* arow = &g_A2[(size_t)r * 192];
        uint2 gpack;
        *(__half2*)&gpack.x = __floats2half2_rn(f0 * 0.0625f, f1 * 0.0625f);
        *(__half2*)&gpack.y = __floats2half2_rn(f2 * 0.0625f, f3 * 0.0625f);
        *(uint2*)&arow[lane * 4] = gpack;
        *(__half2*)&arow[128 + lane * 2] = __floats2half2_rn(s0 * 0.0625f, s1 * 0.0625f);

        idx = idx_next;
    }
}

// ---------------------------------------------------------------------------
// Kernel 3: persistent double-buffered GEMM  out = relu([xh|A2] @ W^T)
// W in smem once per SM; 64-row A chunks prefetched via cp.async while the
// previous chunk runs HMMA. 16 warps = 4 m-tiles x 4 n-quarters.
// ---------------------------------------------------------------------------
__device__ __forceinline__ uint32_t smem_u32(const void* p) {
    uint32_t a;
    asm("{ .reg .u64 t; cvta.to.shared.u64 t, %1; cvt.u32.u64 %0, t; }"
        : "=r"(a) : "l"(p));
    return a;
}

__device__ __forceinline__ void cp16(uint32_t dst, const void* src) {
    asm volatile("cp.async.cg.shared.global [%0], [%1], 16;"
                 :: "r"(dst), "l"(src));
}

extern __shared__ __half smem[];

__global__ void __launch_bounds__(512, 1)
gemm_kernel(float* __restrict__ out) {
    __half* Wsm = smem;                                   // [128][AS]
    __half* Ab0 = smem + 128 * AS;                        // [64][AS]
    __half* Ab1 = smem + 128 * AS + CHUNK_ROWS * AS;      // [64][AS]
    const uint32_t abase[2] = { smem_u32(Ab0), smem_u32(Ab1) };

    const int tid  = threadIdx.x;
    const int lane = tid & 31;
    const int warp = tid >> 5;

    // ---- W: packed weights -> smem (once per persistent CTA) ----
    {
        const int4* wsrc = (const int4*)g_wh;   // 5120 int4
        for (int i = tid; i < 5120; i += 512) {
            int row = i / 40, c = i % 40;
            *(int4*)&Wsm[row * AS + c * 8] = wsrc[i];
        }
    }

    // ---- prologue: async-load first chunk into buf 0 ----
    int c = blockIdx.x;
    {
        int base = c * CHUNK_ROWS;
        for (int i = tid; i < 2560; i += 512) {        // 64 rows * 40 int4
            int row = i / 40, cc = i % 40;
            int r = base + row; if (r > NTOT - 1) r = NTOT - 1;
            const void* src = (cc < 16)
                ? (const void*)&g_xh[(size_t)r * XNIN + cc * 8]
                : (const void*)&g_A2[(size_t)r * 192 + (cc - 16) * 8];
            cp16(abase[0] + (uint32_t)(row * AS + cc * 8) * 2u, src);
        }
    }
    asm volatile("cp.async.commit_group;" ::: "memory");

    const int g  = lane >> 2;
    const int tg = lane & 3;
    const int mq = warp >> 2;     // 0..3 : 16-row m-tile within chunk
    const int nq = warp & 3;      // 0..3 : 32-col n-quarter
    const int wm = mq * 16;

    int buf = 0;
    for (; c < NCH; c += GRID_G) {
        // ---- prefetch next chunk into the other buffer ----
        int cn = c + GRID_G;
        if (cn < NCH) {
            int base = cn * CHUNK_ROWS;
            for (int i = tid; i < 2560; i += 512) {
                int row = i / 40, cc = i % 40;
                int r = base + row; if (r > NTOT - 1) r = NTOT - 1;
                const void* src = (cc < 16)
                    ? (const void*)&g_xh[(size_t)r * XNIN + cc * 8]
                    : (const void*)&g_A2[(size_t)r * 192 + (cc - 16) * 8];
                cp16(abase[buf ^ 1] + (uint32_t)(row * AS + cc * 8) * 2u, src);
            }
        }
        asm volatile("cp.async.commit_group;" ::: "memory");
        asm volatile("cp.async.wait_group 1;" ::: "memory");   // current buf ready
        __syncthreads();

        // ---- MMA on current buffer ----
        const __half* Asm = (buf == 0) ? Ab0 : Ab1;
        float acc[4][4];
        #pragma unroll
        for (int t = 0; t < 4; t++)
            acc[t][0] = acc[t][1] = acc[t][2] = acc[t][3] = 0.f;

        #pragma unroll 4
        for (int k0 = 0; k0 < KTOT; k0 += 16) {
            uint32_t a0 = *(const uint32_t*)&Asm[(wm + g)     * AS + k0 +     tg * 2];
            uint32_t a1 = *(const uint32_t*)&Asm[(wm + g + 8) * AS + k0 +     tg * 2];
            uint32_t a2 = *(const uint32_t*)&Asm[(wm + g)     * AS + k0 + 8 + tg * 2];
            uint32_t a3 = *(const uint32_t*)&Asm[(wm + g + 8) * AS + k0 + 8 + tg * 2];
            #pragma unroll
            for (int t = 0; t < 4; t++) {
                int nrow = nq * 32 + t * 8 + g;
                uint32_t b0 = *(const uint32_t*)&Wsm[nrow * AS + k0 +     tg * 2];
                uint32_t b1 = *(const uint32_t*)&Wsm[nrow * AS + k0 + 8 + tg * 2];
                asm volatile(
                    "mma.sync.aligned.m16n8k16.row.col.f32.f16.f16.f32 "
                    "{%0,%1,%2,%3},{%4,%5,%6,%7},{%8,%9},{%0,%1,%2,%3};\n"
                    : "+f"(acc[t][0]), "+f"(acc[t][1]), "+f"(acc[t][2]), "+f"(acc[t][3])
                    : "r"(a0), "r"(a1), "r"(a2), "r"(a3), "r"(b0), "r"(b1));
            }
        }

        // ---- store with relu ----
        int rbase = c * CHUNK_ROWS;
        #pragma unroll
        for (int t = 0; t < 4; t++) {
            int col  = nq * 32 + t * 8 + tg * 2;
            int row0 = rbase + wm + g;
            int row1 = row0 + 8;
            if (row0 < NTOT) {
                float2 v;
                v.x = fmaxf(acc[t][0], 0.f);
                v.y = fmaxf(acc[t][1], 0.f);
                __stcs((float2*)&out[(size_t)row0 * XNOUT + col], v);
            }
            if (row1 < NTOT) {
                float2 v;
                v.x = fmaxf(acc[t][2], 0.f);
                v.y = fmaxf(acc[t][3], 0.f);
                __stcs((float2*)&out[(size_t)row1 * XNOUT + col], v);
            }
        }

        __syncthreads();   // all LDS reads of this buffer done before reuse
        buf ^= 1;
    }
}

// ---------------------------------------------------------------------------
extern "C" void kernel_launch(void* const* d_in, const int* in_sizes, int n_in,
                              void* d_out, int out_size) {
    const float* x  = (const float*)d_in[0];
    const float* e  = (const float*)d_in[1];
    const int*   ij = (const int*)d_in[2];     // int32 (JAX x64 disabled)
    const float* Wc = (const float*)d_in[3];
    const float* Wn = (const float*)d_in[4];
    const float* We = (const float*)d_in[5];
    float* out = (float*)d_out;
    (void)in_sizes; (void)n_in; (void)out_size;

    prep_kernel<<<2048, 256>>>(x, Wc, Wn, We);

    build_kernel<<<2048, 256>>>(e, ij);

    const int smem_bytes = (128 + 2 * CHUNK_ROWS) * AS * (int)sizeof(__half); // 167936
    cudaFuncSetAttribute(gemm_kernel,
                         cudaFuncAttributeMaxDynamicSharedMemorySize, smem_bytes);
    gemm_kernel<<<GRID_G, 512, smem_bytes>>>(out);
}